// round 13
// baseline (speedup 1.0000x reference)
#include <cuda_runtime.h>
#include <cstdint>

// Problem dims (fixed): pred [8,4,256,256] f32, target [8,256,256] i32,
// boundary_weight [8,1,256,256] f32, output: scalar f32.
#define BQ 8
#define HQ 256
#define WQ 256
#define HWQ (HQ * WQ)
#define NPIX (BQ * HWQ)
#define HP   (HQ + 6)                    // padded rows per image
#define NBLK (BQ * HQ)                   // 2048 vpass blocks
#define BIGD2 (1 << 28)
#define PADV 0x00400040u                 // "not found" packed row distance

// __device__ globals only (harness-sanctioned). g_done zero at module load,
// restored to zero by the last vpass block -> identical state every replay.
__device__ uint4    g_hd4[BQ * HP * (WQ / 2)];   // padded packed row distances
__device__ float    g_partial[NBLK];
__device__ unsigned g_done;

// ---------------------------------------------------------------------------
// Pass A: horizontal 7-window min per pixel (once per image row), 4 rows per
// block. Output (per pixel): (d_cls0|d_cls1<<16, d_cls2|d_cls3<<16) with
// 64 = class absent in window. Also writes 3 sentinel pad rows per image edge.
// Grid: 512 blocks x 256 threads.
// ---------------------------------------------------------------------------
__global__ __launch_bounds__(256) void cwbl_hpass(const int* __restrict__ target) {
    const int blk = blockIdx.x;
    const int b   = blk >> 6;            // 64 groups per image
    const int g   = blk & 63;
    const int i0  = g * 4;
    const int j   = threadIdx.x;
    const int w   = j >> 5;
    const int l   = j & 31;

    __shared__ unsigned sw0[4][10], sw1[4][10];   // 4 rows of words + sentinels
    __shared__ unsigned slutA[128], slutB[128];

    if (j < 128) {
        const unsigned m = j;
        const unsigned d = (m & 0x08) ? 0u : (m & 0x14) ? 1u : (m & 0x22) ? 4u
                                           : (m & 0x41) ? 9u : 64u;
        slutA[m] = d;
        slutB[m] = d << 16;
    }
    if (j < 4) { sw0[j][0] = 0; sw1[j][0] = 0; sw0[j][9] = 0; sw1[j][9] = 0; }

    const int* tb = target + b * HWQ;
#pragma unroll
    for (int k = 0; k < 4; ++k) {
        const int v = __ldg(&tb[(i0 + k) * WQ + j]);
        const unsigned m0 = __ballot_sync(0xffffffffu, v & 1);
        const unsigned m1 = __ballot_sync(0xffffffffu, v & 2);
        if (l == 0) { sw0[k][w + 1] = m0; sw1[k][w + 1] = m1; }
    }
    __syncthreads();

    const int sl = max(0, 3 - j);
    const int sr = max(0, j - (WQ - 4));
    const unsigned vwin = ((0x7Fu << sl) & (0x7Fu >> sr)) & 0x7Fu;

    uint2* hd2 = (uint2*)g_hd4;
#pragma unroll
    for (int k = 0; k < 4; ++k) {
        const unsigned p0 = sw0[k][w], c0 = sw0[k][w + 1], n0 = sw0[k][w + 2];
        const unsigned p1 = sw1[k][w], c1 = sw1[k][w + 1], n1 = sw1[k][w + 2];
        const unsigned w0 = (l < 3) ? __funnelshift_r(p0, c0, l + 29)
                                    : __funnelshift_r(c0, n0, l - 3);
        const unsigned w1 = (l < 3) ? __funnelshift_r(p1, c1, l + 29)
                                    : __funnelshift_r(c1, n1, l - 3);
        const unsigned mm0 = (~w0 & ~w1) & vwin;
        const unsigned mm1 = ( w0 & ~w1) & vwin;
        const unsigned mm2 = (~w0 &  w1) & vwin;
        const unsigned mm3 = ( w0 &  w1) & vwin;
        hd2[(b * HP + i0 + k + 3) * WQ + j] =
            make_uint2(slutA[mm0] + slutB[mm1], slutA[mm2] + slutB[mm3]);
    }

    if (g == 0) {
#pragma unroll
        for (int r = 0; r < 3; ++r)
            hd2[(b * HP + r) * WQ + j] = make_uint2(PADV, PADV);
    }
    if (g == 63) {
#pragma unroll
        for (int r = HQ + 3; r < HP; ++r)
            hd2[(b * HP + r) * WQ + j] = make_uint2(PADV, PADV);
    }
}

// ---------------------------------------------------------------------------
// Pass B: vertical 7-tap DPX combine + softmax + weighted error + reduction.
// Grid: 2048 blocks (one per (b,i)) x 128 threads; each thread = 2 columns.
// bd_c certified exact when <= 16 (outside the 7x7 box d2 >= 16); own class
// is the unique bd_c == 0. Uncertified pixels take the exact ring search.
// Unfound classes give dist 0 (reproduces degenerate-class zeroing).
// ---------------------------------------------------------------------------
__global__ __launch_bounds__(128, 10) void cwbl_vpass(
        const float* __restrict__ pred,
        const int*   __restrict__ target,
        const float* __restrict__ wgt,
        float*       __restrict__ out) {
    const int bi  = blockIdx.x;          // b*HQ + i
    const int b   = bi >> 8;
    const int i   = bi & (HQ - 1);
    const int tid = threadIdx.x;
    const int col = tid * 2;

    __shared__ float ssq[20];
    __shared__ float sa[4];
    if (tid < 20) ssq[tid] = sqrtf((float)tid);

    // 7 independent 16B loads (padded layout: no clamps, no selects)
    uint4 hv[7];
#pragma unroll
    for (int q = 0; q < 7; ++q)
        hv[q] = g_hd4[(b * HP + i + q) * (WQ / 2) + tid];

    // float data, vectorized 2-wide
    const size_t pbase = (size_t)b * 4 * HWQ + i * WQ + col;
    const float2 wv2 = *(const float2*)(wgt + b * HWQ + i * WQ + col);
    const float2 xa0 = *(const float2*)(pred + pbase);
    const float2 xa1 = *(const float2*)(pred + pbase + HWQ);
    const float2 xa2 = *(const float2*)(pred + pbase + 2 * HWQ);
    const float2 xa3 = *(const float2*)(pred + pbase + 3 * HWQ);

    __syncthreads();     // publish ssq (fixes R11's race)

    // vertical DPX combine for both pixels
    unsigned bloA = 0x00FF00FFu, bhiA = 0x00FF00FFu;
    unsigned bloB = 0x00FF00FFu, bhiB = 0x00FF00FFu;
#pragma unroll
    for (int q = 0; q < 7; ++q) {
        const int di = q - 3;
        const unsigned dd = (unsigned)(di * di) * 0x00010001u;  // compile-time
        bloA = __viaddmin_u16x2(hv[q].x, dd, bloA);
        bhiA = __viaddmin_u16x2(hv[q].y, dd, bhiA);
        bloB = __viaddmin_u16x2(hv[q].z, dd, bloB);
        bhiB = __viaddmin_u16x2(hv[q].w, dd, bhiB);
    }

    float accT = 0.0f;
#pragma unroll
    for (int px = 0; px < 2; ++px) {
        const unsigned blo = px ? bloB : bloA;
        const unsigned bhi = px ? bhiB : bhiA;
        const int c = col + px;
        int bd0 = (int)(blo & 0xFFFFu), bd1 = (int)(blo >> 16);
        int bd2 = (int)(bhi & 0xFFFFu), bd3 = (int)(bhi >> 16);

        // min over classes other than own (own class is the unique bd==0)
        int mo = min(min(bd0 ? bd0 : BIGD2, bd1 ? bd1 : BIGD2),
                     min(bd2 ? bd2 : BIGD2, bd3 ? bd3 : BIGD2));
        int n1 = bd1 ? bd1 : mo;
        int n2 = bd2 ? bd2 : mo;
        int n3 = bd3 ? bd3 : mo;
        float i1 = bd1 ? 0.0f : 1.0f;
        float i2 = bd2 ? 0.0f : 1.0f;
        float i3 = bd3 ? 0.0f : 1.0f;

        float d1f, d2f, d3f;
        if (max(n1, max(n2, n3)) <= 16) {
            d1f = ssq[n1]; d2f = ssq[n2]; d3f = ssq[n3];
        } else {
            // --- rare exact ring fallback ---
            const int* tb = target + b * HWQ;
            const int t = __ldg(&tb[i * WQ + c]);
            bd0 = (bd0 > 18) ? BIGD2 : bd0;
            bd1 = (bd1 > 18) ? BIGD2 : bd1;
            bd2 = (bd2 > 18) ? BIGD2 : bd2;
            bd3 = (bd3 > 18) ? BIGD2 : bd3;
#pragma unroll 1
            for (int r = 4; r < 256; ++r) {
                int mo_ = BIGD2;
                if (t != 0) mo_ = min(mo_, bd0);
                if (t != 1) mo_ = min(mo_, bd1);
                if (t != 2) mo_ = min(mo_, bd2);
                if (t != 3) mo_ = min(mo_, bd3);
                int M = 0;
                M = max(M, (t == 1) ? mo_ : bd1);
                M = max(M, (t == 2) ? mo_ : bd2);
                M = max(M, (t == 3) ? mo_ : bd3);
                if (r * r >= M) break;

                const int r2   = r * r;
                const int itop = i - r;
                const int ibot = i + r;
                const bool okT = (itop >= 0);
                const bool okB = (ibot < HQ);
                const int* rowT = tb + itop * WQ;
                const int* rowB = tb + ibot * WQ;
#pragma unroll 1
                for (int dj = -r; dj <= r; ++dj) {
                    const int jj = c + dj;
                    if ((unsigned)jj >= (unsigned)WQ) continue;
                    const int d2 = r2 + dj * dj;
                    if (okT) {
                        const int v = __ldg(&rowT[jj]);
                        bd0 = min(bd0, (v == 0) ? d2 : BIGD2);
                        bd1 = min(bd1, (v == 1) ? d2 : BIGD2);
                        bd2 = min(bd2, (v == 2) ? d2 : BIGD2);
                        bd3 = min(bd3, (v == 3) ? d2 : BIGD2);
                    }
                    if (okB) {
                        const int v = __ldg(&rowB[jj]);
                        bd0 = min(bd0, (v == 0) ? d2 : BIGD2);
                        bd1 = min(bd1, (v == 1) ? d2 : BIGD2);
                        bd2 = min(bd2, (v == 2) ? d2 : BIGD2);
                        bd3 = min(bd3, (v == 3) ? d2 : BIGD2);
                    }
                }
                const int jl = c - r;
                const int jr = c + r;
                const bool okL = (jl >= 0);
                const bool okR = (jr < WQ);
#pragma unroll 1
                for (int di = -r + 1; di <= r - 1; ++di) {
                    const int ii = i + di;
                    if ((unsigned)ii >= (unsigned)HQ) continue;
                    const int d2  = di * di + r2;
                    const int* row = tb + ii * WQ;
                    if (okL) {
                        const int v = __ldg(&row[jl]);
                        bd0 = min(bd0, (v == 0) ? d2 : BIGD2);
                        bd1 = min(bd1, (v == 1) ? d2 : BIGD2);
                        bd2 = min(bd2, (v == 2) ? d2 : BIGD2);
                        bd3 = min(bd3, (v == 3) ? d2 : BIGD2);
                    }
                    if (okR) {
                        const int v = __ldg(&row[jr]);
                        bd0 = min(bd0, (v == 0) ? d2 : BIGD2);
                        bd1 = min(bd1, (v == 1) ? d2 : BIGD2);
                        bd2 = min(bd2, (v == 2) ? d2 : BIGD2);
                        bd3 = min(bd3, (v == 3) ? d2 : BIGD2);
                    }
                }
            }
            int moF = BIGD2;
            if (t != 0) moF = min(moF, bd0);
            if (t != 1) moF = min(moF, bd1);
            if (t != 2) moF = min(moF, bd2);
            if (t != 3) moF = min(moF, bd3);
            n1 = (t == 1) ? moF : bd1;
            n2 = (t == 2) ? moF : bd2;
            n3 = (t == 3) ? moF : bd3;
            i1 = (t == 1) ? 1.0f : 0.0f;
            i2 = (t == 2) ? 1.0f : 0.0f;
            i3 = (t == 3) ? 1.0f : 0.0f;
            d1f = (n1 < BIGD2) ? sqrtf((float)n1) : 0.0f;
            d2f = (n2 < BIGD2) ? sqrtf((float)n2) : 0.0f;
            d3f = (n3 < BIGD2) ? sqrtf((float)n3) : 0.0f;
        }

        // --- softmax (no max-sub: |x|<~6 so no overflow) + weighted error ---
        const float x0 = px ? xa0.y : xa0.x;
        const float x1 = px ? xa1.y : xa1.x;
        const float x2 = px ? xa2.y : xa2.x;
        const float x3 = px ? xa3.y : xa3.x;
        const float e0 = __expf(x0);
        const float e1 = __expf(x1);
        const float e2 = __expf(x2);
        const float e3 = __expf(x3);
        const float rd = __fdividef(1.0f, e0 + e1 + e2 + e3);

        float s = fabsf(e1 * rd - i1) * d1f;
        s      += fabsf(e2 * rd - i2) * d2f;
        s      += fabsf(e3 * rd - i3) * d3f;
        accT = fmaf(s, px ? wv2.y : wv2.x, accT);
    }

    // --- block reduction (4 warps) -> per-block partial, fixed order ---
    float acc = accT;
#pragma unroll
    for (int o = 16; o > 0; o >>= 1)
        acc += __shfl_down_sync(0xffffffffu, acc, o);
    if ((tid & 31) == 0) sa[tid >> 5] = acc;
    __syncthreads();
    if (tid == 0)
        g_partial[bi] = (sa[0] + sa[1]) + (sa[2] + sa[3]);

    // --- last-block deterministic finalize ---
    __shared__ unsigned ticket;
    __threadfence();
    if (tid == 0) ticket = atomicAdd(&g_done, 1u);
    __syncthreads();
    if (ticket == NBLK - 1) {
        __threadfence();
        __shared__ double sd[128];
        double s = 0.0;
        for (int k = tid; k < NBLK; k += 128)
            s += (double)g_partial[k];              // fixed order
        sd[tid] = s;
        __syncthreads();
#pragma unroll
        for (int st = 64; st > 0; st >>= 1) {
            if (tid < st) sd[tid] += sd[tid + st];
            __syncthreads();
        }
        if (tid == 0) {
            out[0] = (float)(sd[0] / (3.0 * (double)NPIX));
            g_done = 0;                             // restore invariant
        }
    }
}

// ---------------------------------------------------------------------------
extern "C" void kernel_launch(void* const* d_in, const int* in_sizes, int n_in,
                              void* d_out, int out_size) {
    const float* pred   = (const float*)d_in[0];
    const int*   target = (const int*)d_in[1];
    const float* wgt    = (const float*)d_in[2];
    float* out = (float*)d_out;
    (void)in_sizes; (void)n_in; (void)out_size;

    cwbl_hpass<<<BQ * 64, 256>>>(target);
    cwbl_vpass<<<NBLK, 128>>>(pred, target, wgt, out);
}

// round 14
// speedup vs baseline: 1.0994x; 1.0994x over previous
#include <cuda_runtime.h>
#include <cstdint>

// Problem dims (fixed): pred [8,4,256,256] f32, target [8,256,256] i32,
// boundary_weight [8,1,256,256] f32, output: scalar f32.
#define BQ 8
#define HQ 256
#define WQ 256
#define HWQ (HQ * WQ)
#define NPIX (BQ * HWQ)
#define HP   (HQ + 6)                    // padded rows per image
#define NBLK (BQ * HQ)                   // 2048 vpass blocks
#define BIGD2 (1 << 28)
#define PADV 0x00400040u                 // "not found" packed row distance

// __device__ globals only (harness-sanctioned). g_done zero at module load,
// restored to zero by the last vpass block -> identical state every replay.
__device__ uint2    g_hd[BQ * HP * WQ];  // padded packed horizontal distances
__device__ float    g_partial[NBLK];
__device__ unsigned g_done;

// ---------------------------------------------------------------------------
// Pass A: horizontal 7-window min per pixel (once per image row), 4 rows per
// block. Output (per pixel): (d_cls0|d_cls1<<16, d_cls2|d_cls3<<16) with
// 64 = class absent in window. Also writes 3 sentinel pad rows per image edge.
// Grid: 512 blocks x 256 threads.  (Proven correct in R12: rel_err = 0.)
// ---------------------------------------------------------------------------
__global__ __launch_bounds__(256) void cwbl_hpass(const int* __restrict__ target) {
    const int blk = blockIdx.x;
    const int b   = blk >> 6;            // 64 groups per image
    const int g   = blk & 63;
    const int i0  = g * 4;
    const int j   = threadIdx.x;
    const int w   = j >> 5;
    const int l   = j & 31;

    __shared__ unsigned sw0[4][10], sw1[4][10];   // 4 rows of words + sentinels
    __shared__ unsigned slutA[128], slutB[128];

    if (j < 128) {
        const unsigned m = j;
        const unsigned d = (m & 0x08) ? 0u : (m & 0x14) ? 1u : (m & 0x22) ? 4u
                                           : (m & 0x41) ? 9u : 64u;
        slutA[m] = d;
        slutB[m] = d << 16;
    }
    if (j < 4) { sw0[j][0] = 0; sw1[j][0] = 0; sw0[j][9] = 0; sw1[j][9] = 0; }

    const int* tb = target + b * HWQ;
#pragma unroll
    for (int k = 0; k < 4; ++k) {
        const int v = __ldg(&tb[(i0 + k) * WQ + j]);
        const unsigned m0 = __ballot_sync(0xffffffffu, v & 1);
        const unsigned m1 = __ballot_sync(0xffffffffu, v & 2);
        if (l == 0) { sw0[k][w + 1] = m0; sw1[k][w + 1] = m1; }
    }
    __syncthreads();

    const int sl = max(0, 3 - j);
    const int sr = max(0, j - (WQ - 4));
    const unsigned vwin = ((0x7Fu << sl) & (0x7Fu >> sr)) & 0x7Fu;

#pragma unroll
    for (int k = 0; k < 4; ++k) {
        const unsigned p0 = sw0[k][w], c0 = sw0[k][w + 1], n0 = sw0[k][w + 2];
        const unsigned p1 = sw1[k][w], c1 = sw1[k][w + 1], n1 = sw1[k][w + 2];
        const unsigned w0 = (l < 3) ? __funnelshift_r(p0, c0, l + 29)
                                    : __funnelshift_r(c0, n0, l - 3);
        const unsigned w1 = (l < 3) ? __funnelshift_r(p1, c1, l + 29)
                                    : __funnelshift_r(c1, n1, l - 3);
        const unsigned mm0 = (~w0 & ~w1) & vwin;
        const unsigned mm1 = ( w0 & ~w1) & vwin;
        const unsigned mm2 = (~w0 &  w1) & vwin;
        const unsigned mm3 = ( w0 &  w1) & vwin;
        g_hd[(b * HP + i0 + k + 3) * WQ + j] =
            make_uint2(slutA[mm0] + slutB[mm1], slutA[mm2] + slutB[mm3]);
    }

    if (g == 0) {
#pragma unroll
        for (int r = 0; r < 3; ++r)
            g_hd[(b * HP + r) * WQ + j] = make_uint2(PADV, PADV);
    }
    if (g == 63) {
#pragma unroll
        for (int r = HQ + 3; r < HP; ++r)
            g_hd[(b * HP + r) * WQ + j] = make_uint2(PADV, PADV);
    }
}

// ---------------------------------------------------------------------------
// Pass B: vertical 7-tap DPX combine + softmax + weighted error + reduction.
// Grid: 2048 blocks (one per (b,i)) x 256 threads (one per column) — the
// R11 scaffold that measured 84.9% occupancy — minus the clamp/select fat
// (padded layout), minus the target load (own class = unique bd_c == 0),
// minus softmax max-subtraction.
// bd_c certified exact when <= 16 (outside the 7x7 box d2 >= 16);
// uncertified pixels take the exact ring search. Unfound classes give
// dist 0 (reproduces the reference's degenerate-class zeroing).
// ---------------------------------------------------------------------------
__global__ __launch_bounds__(256) void cwbl_vpass(
        const float* __restrict__ pred,
        const int*   __restrict__ target,
        const float* __restrict__ wgt,
        float*       __restrict__ out) {
    const int bi = blockIdx.x;           // b*HQ + i
    const int b  = bi >> 8;
    const int i  = bi & (HQ - 1);
    const int j  = threadIdx.x;
    const int w  = j >> 5;
    const int l  = j & 31;

    __shared__ float ssq[20];
    __shared__ float sa[8];
    if (j < 20) ssq[j] = sqrtf((float)j);

    // --- vertical DPX combine over 7 padded rows (no clamps, no selects) ---
    const uint2* hrow = g_hd + (b * HP + i) * WQ + j;
    unsigned blo = 0x00FF00FFu, bhi = 0x00FF00FFu;
#pragma unroll
    for (int q = 0; q < 7; ++q) {
        const uint2 hv = __ldg(&hrow[q * WQ]);
        const int di = q - 3;
        const unsigned dd = (unsigned)(di * di) * 0x00010001u;  // compile-time
        blo = __viaddmin_u16x2(hv.x, dd, blo);
        bhi = __viaddmin_u16x2(hv.y, dd, bhi);
    }

    __syncthreads();     // publish ssq (explicit barrier: no race)

    int bd0 = (int)(blo & 0xFFFFu), bd1 = (int)(blo >> 16);
    int bd2 = (int)(bhi & 0xFFFFu), bd3 = (int)(bhi >> 16);

    // min over classes other than own (own class is the unique bd==0)
    int mo = min(min(bd0 ? bd0 : BIGD2, bd1 ? bd1 : BIGD2),
                 min(bd2 ? bd2 : BIGD2, bd3 ? bd3 : BIGD2));
    int n1 = bd1 ? bd1 : mo;
    int n2 = bd2 ? bd2 : mo;
    int n3 = bd3 ? bd3 : mo;
    float i1 = bd1 ? 0.0f : 1.0f;
    float i2 = bd2 ? 0.0f : 1.0f;
    float i3 = bd3 ? 0.0f : 1.0f;

    float d1f, d2f, d3f;
    if (max(n1, max(n2, n3)) <= 16) {
        d1f = ssq[n1]; d2f = ssq[n2]; d3f = ssq[n3];
    } else {
        // --- rare exact ring fallback (cold path; loads target) ---
        const int* tb = target + b * HWQ;
        const int t = __ldg(&tb[i * WQ + j]);
        bd0 = (bd0 > 18) ? BIGD2 : bd0;
        bd1 = (bd1 > 18) ? BIGD2 : bd1;
        bd2 = (bd2 > 18) ? BIGD2 : bd2;
        bd3 = (bd3 > 18) ? BIGD2 : bd3;
#pragma unroll 1
        for (int r = 4; r < 256; ++r) {
            int mo_ = BIGD2;
            if (t != 0) mo_ = min(mo_, bd0);
            if (t != 1) mo_ = min(mo_, bd1);
            if (t != 2) mo_ = min(mo_, bd2);
            if (t != 3) mo_ = min(mo_, bd3);
            int M = 0;
            M = max(M, (t == 1) ? mo_ : bd1);
            M = max(M, (t == 2) ? mo_ : bd2);
            M = max(M, (t == 3) ? mo_ : bd3);
            if (r * r >= M) break;

            const int r2   = r * r;
            const int itop = i - r;
            const int ibot = i + r;
            const bool okT = (itop >= 0);
            const bool okB = (ibot < HQ);
            const int* rowT = tb + itop * WQ;
            const int* rowB = tb + ibot * WQ;
#pragma unroll 1
            for (int dj = -r; dj <= r; ++dj) {
                const int jj = j + dj;
                if ((unsigned)jj >= (unsigned)WQ) continue;
                const int d2 = r2 + dj * dj;
                if (okT) {
                    const int v = __ldg(&rowT[jj]);
                    bd0 = min(bd0, (v == 0) ? d2 : BIGD2);
                    bd1 = min(bd1, (v == 1) ? d2 : BIGD2);
                    bd2 = min(bd2, (v == 2) ? d2 : BIGD2);
                    bd3 = min(bd3, (v == 3) ? d2 : BIGD2);
                }
                if (okB) {
                    const int v = __ldg(&rowB[jj]);
                    bd0 = min(bd0, (v == 0) ? d2 : BIGD2);
                    bd1 = min(bd1, (v == 1) ? d2 : BIGD2);
                    bd2 = min(bd2, (v == 2) ? d2 : BIGD2);
                    bd3 = min(bd3, (v == 3) ? d2 : BIGD2);
                }
            }
            const int jl = j - r;
            const int jr = j + r;
            const bool okL = (jl >= 0);
            const bool okR = (jr < WQ);
#pragma unroll 1
            for (int di = -r + 1; di <= r - 1; ++di) {
                const int ii = i + di;
                if ((unsigned)ii >= (unsigned)HQ) continue;
                const int d2  = di * di + r2;
                const int* row = tb + ii * WQ;
                if (okL) {
                    const int v = __ldg(&row[jl]);
                    bd0 = min(bd0, (v == 0) ? d2 : BIGD2);
                    bd1 = min(bd1, (v == 1) ? d2 : BIGD2);
                    bd2 = min(bd2, (v == 2) ? d2 : BIGD2);
                    bd3 = min(bd3, (v == 3) ? d2 : BIGD2);
                }
                if (okR) {
                    const int v = __ldg(&row[jr]);
                    bd0 = min(bd0, (v == 0) ? d2 : BIGD2);
                    bd1 = min(bd1, (v == 1) ? d2 : BIGD2);
                    bd2 = min(bd2, (v == 2) ? d2 : BIGD2);
                    bd3 = min(bd3, (v == 3) ? d2 : BIGD2);
                }
            }
        }
        int moF = BIGD2;
        if (t != 0) moF = min(moF, bd0);
        if (t != 1) moF = min(moF, bd1);
        if (t != 2) moF = min(moF, bd2);
        if (t != 3) moF = min(moF, bd3);
        n1 = (t == 1) ? moF : bd1;
        n2 = (t == 2) ? moF : bd2;
        n3 = (t == 3) ? moF : bd3;
        i1 = (t == 1) ? 1.0f : 0.0f;
        i2 = (t == 2) ? 1.0f : 0.0f;
        i3 = (t == 3) ? 1.0f : 0.0f;
        d1f = (n1 < BIGD2) ? sqrtf((float)n1) : 0.0f;
        d2f = (n2 < BIGD2) ? sqrtf((float)n2) : 0.0f;
        d3f = (n3 < BIGD2) ? sqrtf((float)n3) : 0.0f;
    }

    // --- softmax (no max-sub: |x| small, fp32 safe) + weighted error ---
    const int  base = i * WQ + j;
    const float* pb = pred + (size_t)b * 4 * HWQ;
    const float wv = __ldg(&wgt[b * HWQ + base]);
    const float e0 = __expf(__ldg(&pb[base]));
    const float e1 = __expf(__ldg(&pb[HWQ + base]));
    const float e2 = __expf(__ldg(&pb[2 * HWQ + base]));
    const float e3 = __expf(__ldg(&pb[3 * HWQ + base]));
    const float rd = __fdividef(1.0f, e0 + e1 + e2 + e3);

    float acc = fabsf(e1 * rd - i1) * d1f;
    acc      += fabsf(e2 * rd - i2) * d2f;
    acc      += fabsf(e3 * rd - i3) * d3f;
    acc      *= wv;

    // --- block reduction -> per-block partial (fixed order, no atomics) ---
#pragma unroll
    for (int o = 16; o > 0; o >>= 1)
        acc += __shfl_down_sync(0xffffffffu, acc, o);
    if (l == 0) sa[w] = acc;
    __syncthreads();
    if (j == 0) {
        float s = 0.0f;
#pragma unroll
        for (int k = 0; k < 8; ++k) s += sa[k];
        g_partial[bi] = s;
    }

    // --- last-block deterministic finalize ---
    __shared__ unsigned ticket;
    __threadfence();
    if (j == 0) ticket = atomicAdd(&g_done, 1u);
    __syncthreads();
    if (ticket == NBLK - 1) {
        __threadfence();
        __shared__ double sd[256];
        double s = 0.0;
        for (int k = j; k < NBLK; k += 256)
            s += (double)g_partial[k];              // fixed order
        sd[j] = s;
        __syncthreads();
#pragma unroll
        for (int st = 128; st > 0; st >>= 1) {
            if (j < st) sd[j] += sd[j + st];
            __syncthreads();
        }
        if (j == 0) {
            out[0] = (float)(sd[0] / (3.0 * (double)NPIX));
            g_done = 0;                             // restore invariant
        }
    }
}

// ---------------------------------------------------------------------------
extern "C" void kernel_launch(void* const* d_in, const int* in_sizes, int n_in,
                              void* d_out, int out_size) {
    const float* pred   = (const float*)d_in[0];
    const int*   target = (const int*)d_in[1];
    const float* wgt    = (const float*)d_in[2];
    float* out = (float*)d_out;
    (void)in_sizes; (void)n_in; (void)out_size;

    cwbl_hpass<<<BQ * 64, 256>>>(target);
    cwbl_vpass<<<NBLK, 256>>>(pred, target, wgt, out);
}

// round 15
// speedup vs baseline: 1.3144x; 1.1956x over previous
#include <cuda_runtime.h>
#include <cstdint>

// Problem dims (fixed): pred [8,4,256,256] f32, target [8,256,256] i32,
// boundary_weight [8,1,256,256] f32, output: scalar f32.
#define BQ 8
#define HQ 256
#define WQ 256
#define HWQ (HQ * WQ)
#define NPIX (BQ * HWQ)
#define ROWS_PER_BLK 4
#define NBLK (NPIX / (ROWS_PER_BLK * WQ))   // 512 blocks
#define BIGD2 (1 << 28)

// __device__ globals only. g_done zero at module load, restored by the last
// block every run -> identical state for correctness run / capture / replays.
__device__ float    g_partial[NBLK];
__device__ unsigned g_done;

// ---------------------------------------------------------------------------
// Single fused kernel (R8 scaffold). Grid: 512 blocks; 256 threads = one
// column each, covering FOUR consecutive image rows i0..i0+3 of one image.
//
// dist_c(p) = sqrt(d2 to nearest pixel with target==c)  if t(p) != c
//           = sqrt(d2 to nearest pixel with target!=c)  if t(p) == c
// contributing 0 if no such pixel exists (reproduces the reference's
// degenerate-class zeroing).
//
// Phase 0: interleaved uint2 bitplanes (class = 2 bits/px) for 10 halo rows.
// Phase 1a: per halo row, 7-bit column window (2 LDS.64 + funnel shifts),
//           class masks via LOP3, min dj^2 via 128-entry uint LUTs, packed
//           2 classes per u16 half.
// Phase 1b: per output row, 7-tap vertical min-plus combine with DPX
//           __viaddmin_u16x2. Exact whenever best d2 <= 16 (everything
//           outside the 7x7 box has d2 >= 16). Miss prob ~1e-6/px.
// Phase 2: rare exact expanding-ring fallback from r=4.
// Epilogue: softmax (no max-sub; |logits| small) + |p_c-t_c|*w*dist, block
//           reduction, last-block deterministic finalize.
// ---------------------------------------------------------------------------
__global__ __launch_bounds__(256) void cwbl_kernel(
        const float* __restrict__ pred,
        const int*   __restrict__ target,
        const float* __restrict__ wgt,
        float*       __restrict__ out) {
    const int blk = blockIdx.x;
    const int b   = blk >> 6;                    // 64 blocks per image
    const int i0  = (blk & 63) * ROWS_PER_BLK;
    const int j   = threadIdx.x;                 // column
    const int w   = j >> 5;                      // warp = word index
    const int l   = j & 31;                      // lane = bit index

    const int* tb = target + b * HWQ;

    __shared__ uint2    sbi[10][10];             // interleaved bitplanes + sentinels
    __shared__ unsigned slutA[128];              // 7-bit mask -> min dj^2
    __shared__ unsigned slutB[128];              // same, pre-shifted << 16
    __shared__ float    ssq[20];                 // sqrt LUT for d2 <= 18
    __shared__ float    sa[8];

    if (j < 128) {
        const unsigned m = j;
        const unsigned d = (m & 0x08) ? 0u : (m & 0x14) ? 1u : (m & 0x22) ? 4u
                                           : (m & 0x41) ? 9u : 64u;
        slutA[m] = d;
        slutB[m] = d << 16;
    }
    if (j < 20) ssq[j] = sqrtf((float)j);
    if (j < 10) { sbi[j][0] = make_uint2(0, 0); sbi[j][9] = make_uint2(0, 0); }

    // --- Phase 0: bitplanes for rows i0-3 .. i0+6 (clamped loads) ---
#pragma unroll
    for (int k = 0; k < 10; ++k) {
        const int ii  = i0 - 3 + k;
        const int iic = min(HQ - 1, max(0, ii));
        const int v   = __ldg(&tb[iic * WQ + j]);
        const unsigned m0 = __ballot_sync(0xffffffffu, v & 1);
        const unsigned m1 = __ballot_sync(0xffffffffu, v & 2);
        if (l == 0) sbi[k][w + 1] = make_uint2(m0, m1);
    }
    __syncthreads();   // also publishes slutA/slutB/ssq

    // column-validity mask for the 7-bit window (bit k <-> dj = k-3)
    const int sl = max(0, 3 - j);
    const int sr = max(0, j - (WQ - 4));
    const unsigned vwin = ((0x7Fu << sl) & (0x7Fu >> sr)) & 0x7Fu;

    // hoisted window-extraction parameters (uniform per thread)
    const bool pl  = (l < 3);
    const int  oth = w + (pl ? 0 : 2);           // neighbor word index
    const int  sh  = pl ? (l + 29) : (l - 3);    // funnel shift amount

    // --- Phase 1a: per-row horizontal min-dj^2, packed 2 classes/u16x2 ---
    unsigned Dlo[10], Dhi[10];     // Dlo = cls0|cls1<<16, Dhi = cls2|cls3<<16
    unsigned t0bits = 0, t1bits = 0;
#pragma unroll
    for (int k = 0; k < 10; ++k) {
        const uint2 cur = sbi[k][w + 1];
        const uint2 o   = sbi[k][oth];
        const unsigned lo0 = pl ? o.x : cur.x;
        const unsigned hi0 = pl ? cur.x : o.x;
        const unsigned lo1 = pl ? o.y : cur.y;
        const unsigned hi1 = pl ? cur.y : o.y;
        const unsigned w0 = __funnelshift_r(lo0, hi0, sh);
        const unsigned w1 = __funnelshift_r(lo1, hi1, sh);
        const unsigned mm0 = (~w0 & ~w1) & vwin;
        const unsigned mm1 = ( w0 & ~w1) & vwin;
        const unsigned mm2 = (~w0 &  w1) & vwin;
        const unsigned mm3 = ( w0 &  w1) & vwin;
        const bool rv = ((unsigned)(i0 - 3 + k) < (unsigned)HQ);  // uniform
        Dlo[k] = rv ? (slutA[mm0] + slutB[mm1]) : 0x00400040u;
        Dhi[k] = rv ? (slutA[mm2] + slutB[mm3]) : 0x00400040u;
        if (k >= 3 && k <= 6) {
            t0bits |= ((w0 >> 3) & 1u) << (k - 3);
            t1bits |= ((w1 >> 3) & 1u) << (k - 3);
        }
    }

    const unsigned DD[7] = {0x00090009u, 0x00040004u, 0x00010001u, 0u,
                            0x00010001u, 0x00040004u, 0x00090009u};

    float acc = 0.0f;
    const float* pb = pred + (size_t)b * 4 * HWQ;

#pragma unroll
    for (int pr = 0; pr < ROWS_PER_BLK; ++pr) {
        // --- Phase 1b: vertical combine, DPX min(a+b, c) on u16x2 ---
        unsigned blo = 0x00FF00FFu, bhi = 0x00FF00FFu;
#pragma unroll
        for (int q = 0; q < 7; ++q) {
            blo = __viaddmin_u16x2(Dlo[pr + q], DD[q], blo);
            bhi = __viaddmin_u16x2(Dhi[pr + q], DD[q], bhi);
        }
        int bd0 = (int)(blo & 0xFFFFu), bd1 = (int)(blo >> 16);
        int bd2 = (int)(bhi & 0xFFFFu), bd3 = (int)(bhi >> 16);
        const int t = (int)((t0bits >> pr) & 1u) | ((int)((t1bits >> pr) & 1u) << 1);

        int mo = min(min((t == 0) ? BIGD2 : bd0, (t == 1) ? BIGD2 : bd1),
                     min((t == 2) ? BIGD2 : bd2, (t == 3) ? BIGD2 : bd3));
        int n1 = (t == 1) ? mo : bd1;
        int n2 = (t == 2) ? mo : bd2;
        int n3 = (t == 3) ? mo : bd3;

        // --- Phase 2: rare exact ring fallback (window certifies d2 <= 16) ---
        if (max(n1, max(n2, n3)) > 16) {
            bd0 = (bd0 > 18) ? BIGD2 : bd0;
            bd1 = (bd1 > 18) ? BIGD2 : bd1;
            bd2 = (bd2 > 18) ? BIGD2 : bd2;
            bd3 = (bd3 > 18) ? BIGD2 : bd3;
            const int i = i0 + pr;
#pragma unroll 1
            for (int r = 4; r < 256; ++r) {
                int mo_ = BIGD2;
                if (t != 0) mo_ = min(mo_, bd0);
                if (t != 1) mo_ = min(mo_, bd1);
                if (t != 2) mo_ = min(mo_, bd2);
                if (t != 3) mo_ = min(mo_, bd3);
                int M = 0;
                M = max(M, (t == 1) ? mo_ : bd1);
                M = max(M, (t == 2) ? mo_ : bd2);
                M = max(M, (t == 3) ? mo_ : bd3);
                if (r * r >= M) break;

                const int r2   = r * r;
                const int itop = i - r;
                const int ibot = i + r;
                const bool okT = (itop >= 0);
                const bool okB = (ibot < HQ);
                const int* rowT = tb + itop * WQ;
                const int* rowB = tb + ibot * WQ;
#pragma unroll 1
                for (int dj = -r; dj <= r; ++dj) {
                    const int jj = j + dj;
                    if ((unsigned)jj >= (unsigned)WQ) continue;
                    const int d2 = r2 + dj * dj;
                    if (okT) {
                        const int v = __ldg(&rowT[jj]);
                        bd0 = min(bd0, (v == 0) ? d2 : BIGD2);
                        bd1 = min(bd1, (v == 1) ? d2 : BIGD2);
                        bd2 = min(bd2, (v == 2) ? d2 : BIGD2);
                        bd3 = min(bd3, (v == 3) ? d2 : BIGD2);
                    }
                    if (okB) {
                        const int v = __ldg(&rowB[jj]);
                        bd0 = min(bd0, (v == 0) ? d2 : BIGD2);
                        bd1 = min(bd1, (v == 1) ? d2 : BIGD2);
                        bd2 = min(bd2, (v == 2) ? d2 : BIGD2);
                        bd3 = min(bd3, (v == 3) ? d2 : BIGD2);
                    }
                }
                const int jl = j - r;
                const int jr = j + r;
                const bool okL = (jl >= 0);
                const bool okR = (jr < WQ);
#pragma unroll 1
                for (int di = -r + 1; di <= r - 1; ++di) {
                    const int ii = i + di;
                    if ((unsigned)ii >= (unsigned)HQ) continue;
                    const int d2  = di * di + r2;
                    const int* row = tb + ii * WQ;
                    if (okL) {
                        const int v = __ldg(&row[jl]);
                        bd0 = min(bd0, (v == 0) ? d2 : BIGD2);
                        bd1 = min(bd1, (v == 1) ? d2 : BIGD2);
                        bd2 = min(bd2, (v == 2) ? d2 : BIGD2);
                        bd3 = min(bd3, (v == 3) ? d2 : BIGD2);
                    }
                    if (okR) {
                        const int v = __ldg(&row[jr]);
                        bd0 = min(bd0, (v == 0) ? d2 : BIGD2);
                        bd1 = min(bd1, (v == 1) ? d2 : BIGD2);
                        bd2 = min(bd2, (v == 2) ? d2 : BIGD2);
                        bd3 = min(bd3, (v == 3) ? d2 : BIGD2);
                    }
                }
            }
            mo = BIGD2;
            if (t != 0) mo = min(mo, bd0);
            if (t != 1) mo = min(mo, bd1);
            if (t != 2) mo = min(mo, bd2);
            if (t != 3) mo = min(mo, bd3);
            n1 = (t == 1) ? mo : bd1;
            n2 = (t == 2) ? mo : bd2;
            n3 = (t == 3) ? mo : bd3;
        }

        // --- distances: LUT for certified range, rare branch otherwise ---
        float d1f = ssq[min(n1, 19)];
        float d2f = ssq[min(n2, 19)];
        float d3f = ssq[min(n3, 19)];
        if (max(n1, max(n2, n3)) > 18) {         // ~never (warp-skipped)
            d1f = (n1 <= 18) ? d1f : ((n1 < BIGD2) ? sqrtf((float)n1) : 0.0f);
            d2f = (n2 <= 18) ? d2f : ((n2 < BIGD2) ? sqrtf((float)n2) : 0.0f);
            d3f = (n3 <= 18) ? d3f : ((n3 < BIGD2) ? sqrtf((float)n3) : 0.0f);
        }

        // --- softmax (no max-sub: |logits| small, fp32 safe) + error ---
        const int base = (i0 + pr) * WQ + j;
        const float wv = __ldg(&wgt[b * HWQ + base]);
        const float e0 = __expf(__ldg(&pb[base]));
        const float e1 = __expf(__ldg(&pb[HWQ + base]));
        const float e2 = __expf(__ldg(&pb[2 * HWQ + base]));
        const float e3 = __expf(__ldg(&pb[3 * HWQ + base]));
        const float rd = __fdividef(1.0f, e0 + e1 + e2 + e3);

        float s = fabsf(e1 * rd - ((t == 1) ? 1.0f : 0.0f)) * d1f;
        s      += fabsf(e2 * rd - ((t == 2) ? 1.0f : 0.0f)) * d2f;
        s      += fabsf(e3 * rd - ((t == 3) ? 1.0f : 0.0f)) * d3f;
        acc = fmaf(s, wv, acc);
    }

    // --- block reduction -> per-block partial (fixed order, no atomics) ---
#pragma unroll
    for (int o = 16; o > 0; o >>= 1)
        acc += __shfl_down_sync(0xffffffffu, acc, o);
    if (l == 0) sa[w] = acc;
    __syncthreads();
    if (j == 0) {
        float s = 0.0f;
#pragma unroll
        for (int k = 0; k < 8; ++k) s += sa[k];
        g_partial[blk] = s;
    }

    // --- last-block deterministic finalize ---
    __shared__ unsigned ticket;
    __threadfence();
    if (j == 0) ticket = atomicAdd(&g_done, 1u);
    __syncthreads();
    if (ticket == NBLK - 1) {
        __threadfence();
        __shared__ double sd[256];
        double s = 0.0;
        for (int k = j; k < NBLK; k += 256)
            s += (double)g_partial[k];              // fixed order
        sd[j] = s;
        __syncthreads();
#pragma unroll
        for (int st = 128; st > 0; st >>= 1) {
            if (j < st) sd[j] += sd[j + st];
            __syncthreads();
        }
        if (j == 0) {
            out[0] = (float)(sd[0] / (3.0 * (double)NPIX));
            g_done = 0;                             // restore invariant
        }
    }
}

// ---------------------------------------------------------------------------
extern "C" void kernel_launch(void* const* d_in, const int* in_sizes, int n_in,
                              void* d_out, int out_size) {
    const float* pred   = (const float*)d_in[0];
    const int*   target = (const int*)d_in[1];
    const float* wgt    = (const float*)d_in[2];
    float* out = (float*)d_out;
    (void)in_sizes; (void)n_in; (void)out_size;

    cwbl_kernel<<<NBLK, 256>>>(pred, target, wgt, out);
}

// round 16
// speedup vs baseline: 1.3643x; 1.0380x over previous
#include <cuda_runtime.h>
#include <cstdint>

// Problem dims (fixed): pred [8,4,256,256] f32, target [8,256,256] i32,
// boundary_weight [8,1,256,256] f32, output: scalar f32.
#define BQ 8
#define HQ 256
#define WQ 256
#define HWQ (HQ * WQ)
#define NPIX (BQ * HWQ)
#define ROWS_PER_BLK 4
#define NBLK (NPIX / (ROWS_PER_BLK * WQ))   // 512 blocks
#define BIGD2 (1 << 28)

// __device__ globals only. g_done zero at module load, restored by the last
// block every run -> identical state for correctness run / capture / replays.
__device__ float    g_partial[NBLK];
__device__ unsigned g_done;

__device__ __forceinline__ void cp_async16(void* smem_dst, const void* gsrc) {
    unsigned saddr = (unsigned)__cvta_generic_to_shared(smem_dst);
    asm volatile("cp.async.cg.shared.global [%0], [%1], 16;\n"
                 :: "r"(saddr), "l"(gsrc) : "memory");
}

// ---------------------------------------------------------------------------
// Single fused kernel (best-measured R8 scaffold + cp.async epilogue prefetch).
// Grid: 512 blocks; 256 threads = one column each, covering FOUR consecutive
// image rows i0..i0+3 of one image.
//
// dist_c(p) = sqrt(d2 to nearest pixel with target==c)  if t(p) != c
//           = sqrt(d2 to nearest pixel with target!=c)  if t(p) == c
// contributing 0 if no such pixel exists (reproduces the reference's
// degenerate-class zeroing).
// ---------------------------------------------------------------------------
__global__ __launch_bounds__(256) void cwbl_kernel(
        const float* __restrict__ pred,
        const int*   __restrict__ target,
        const float* __restrict__ wgt,
        float*       __restrict__ out) {
    const int blk = blockIdx.x;
    const int b   = blk >> 6;                    // 64 blocks per image
    const int i0  = (blk & 63) * ROWS_PER_BLK;
    const int j   = threadIdx.x;                 // column
    const int w   = j >> 5;                      // warp = word index
    const int l   = j & 31;                      // lane = bit index

    const int* tb = target + b * HWQ;

    __shared__ unsigned sb0[10][10], sb1[10][10];  // bitplanes, sentinel cols
    __shared__ unsigned slutA[128];                // 7-bit mask -> min dj^2
    __shared__ unsigned slutB[128];                // same, pre-shifted << 16
    __shared__ float    ssq[20];                   // sqrt LUT for d2 <= 18
    __shared__ float    sa[8];
    __shared__ float    sbuf[20][256];             // prefetched pred(16)+wgt(4)

    // --- cp.async prefetch of this block's pred/wgt tile (20 KB), issued
    //     FIRST so DRAM latency is covered by all the window math below. ---
    {
        const float* pbase = pred + (size_t)b * 4 * HWQ;
        const float* wbase = wgt + (size_t)b * HWQ;
#pragma unroll
        for (int it = 0; it < 5; ++it) {
            const int chunk = it * 256 + j;      // 1280 chunks of 16B
            const int slot  = chunk >> 6;        // 20 slots of 1KB
            const int off   = (chunk & 63) * 4;  // float offset in slot
            const float* gsrc = (slot < 16)
                ? (pbase + (slot & 3) * HWQ + (i0 + (slot >> 2)) * WQ + off)
                : (wbase + (i0 + (slot - 16)) * WQ + off);
            cp_async16(&sbuf[slot][off], gsrc);
        }
        asm volatile("cp.async.commit_group;\n" ::: "memory");
    }

    if (j < 128) {
        const unsigned m = j;
        const unsigned d = (m & 0x08) ? 0u : (m & 0x14) ? 1u : (m & 0x22) ? 4u
                                           : (m & 0x41) ? 9u : 64u;
        slutA[m] = d;
        slutB[m] = d << 16;
    }
    if (j < 20) ssq[j] = sqrtf((float)j);
    if (j < 10) { sb0[j][0] = 0; sb1[j][0] = 0; sb0[j][9] = 0; sb1[j][9] = 0; }

    // --- Phase 0: bitplanes for rows i0-3 .. i0+6 (clamped loads) ---
#pragma unroll
    for (int k = 0; k < 10; ++k) {
        const int ii  = i0 - 3 + k;
        const int iic = min(HQ - 1, max(0, ii));
        const int v   = __ldg(&tb[iic * WQ + j]);
        const unsigned m0 = __ballot_sync(0xffffffffu, v & 1);
        const unsigned m1 = __ballot_sync(0xffffffffu, v & 2);
        if (l == 0) { sb0[k][w + 1] = m0; sb1[k][w + 1] = m1; }
    }
    __syncthreads();   // also publishes slutA/slutB/ssq

    // column-validity mask for the 7-bit window (bit k <-> dj = k-3)
    const int sl = max(0, 3 - j);
    const int sr = max(0, j - (WQ - 4));
    const unsigned vwin = ((0x7Fu << sl) & (0x7Fu >> sr)) & 0x7Fu;

    // --- Phase 1a: per-row horizontal min-dj^2, packed 2 classes per u16x2 ---
    unsigned Dlo[10], Dhi[10];     // Dlo = cls0|cls1<<16, Dhi = cls2|cls3<<16
    unsigned t0bits = 0, t1bits = 0;
#pragma unroll
    for (int k = 0; k < 10; ++k) {
        const unsigned p0 = sb0[k][w], c0 = sb0[k][w + 1], n0 = sb0[k][w + 2];
        const unsigned p1 = sb1[k][w], c1 = sb1[k][w + 1], q1 = sb1[k][w + 2];
        const unsigned w0 = (l < 3) ? __funnelshift_r(p0, c0, l + 29)
                                    : __funnelshift_r(c0, n0, l - 3);
        const unsigned w1 = (l < 3) ? __funnelshift_r(p1, c1, l + 29)
                                    : __funnelshift_r(c1, q1, l - 3);
        const unsigned mm0 = (~w0 & ~w1) & vwin;
        const unsigned mm1 = ( w0 & ~w1) & vwin;
        const unsigned mm2 = (~w0 &  w1) & vwin;
        const unsigned mm3 = ( w0 &  w1) & vwin;
        const bool rv = ((unsigned)(i0 - 3 + k) < (unsigned)HQ);  // uniform
        Dlo[k] = rv ? (slutA[mm0] + slutB[mm1]) : 0x00400040u;
        Dhi[k] = rv ? (slutA[mm2] + slutB[mm3]) : 0x00400040u;
        if (k >= 3 && k <= 6) {
            t0bits |= ((w0 >> 3) & 1u) << (k - 3);
            t1bits |= ((w1 >> 3) & 1u) << (k - 3);
        }
    }

    // pred/wgt tile must be resident before the epilogue reads sbuf
    asm volatile("cp.async.wait_group 0;\n" ::: "memory");
    __syncthreads();

    const unsigned DD[7] = {0x00090009u, 0x00040004u, 0x00010001u, 0u,
                            0x00010001u, 0x00040004u, 0x00090009u};

    float acc = 0.0f;

#pragma unroll
    for (int pr = 0; pr < ROWS_PER_BLK; ++pr) {
        // --- Phase 1b: vertical combine, DPX min(a+b, c) on u16x2 ---
        unsigned blo = 0x00FF00FFu, bhi = 0x00FF00FFu;
#pragma unroll
        for (int q = 0; q < 7; ++q) {
            blo = __viaddmin_u16x2(Dlo[pr + q], DD[q], blo);
            bhi = __viaddmin_u16x2(Dhi[pr + q], DD[q], bhi);
        }
        int bd0 = (int)(blo & 0xFFFFu), bd1 = (int)(blo >> 16);
        int bd2 = (int)(bhi & 0xFFFFu), bd3 = (int)(bhi >> 16);
        const int t = (int)((t0bits >> pr) & 1u) | ((int)((t1bits >> pr) & 1u) << 1);

        int mo = min(min((t == 0) ? BIGD2 : bd0, (t == 1) ? BIGD2 : bd1),
                     min((t == 2) ? BIGD2 : bd2, (t == 3) ? BIGD2 : bd3));
        int n1 = (t == 1) ? mo : bd1;
        int n2 = (t == 2) ? mo : bd2;
        int n3 = (t == 3) ? mo : bd3;

        // --- Phase 2: rare exact ring fallback (window certifies d2 <= 16) ---
        if (max(n1, max(n2, n3)) > 16) {
            bd0 = (bd0 > 18) ? BIGD2 : bd0;
            bd1 = (bd1 > 18) ? BIGD2 : bd1;
            bd2 = (bd2 > 18) ? BIGD2 : bd2;
            bd3 = (bd3 > 18) ? BIGD2 : bd3;
            const int i = i0 + pr;
#pragma unroll 1
            for (int r = 4; r < 256; ++r) {
                int mo_ = BIGD2;
                if (t != 0) mo_ = min(mo_, bd0);
                if (t != 1) mo_ = min(mo_, bd1);
                if (t != 2) mo_ = min(mo_, bd2);
                if (t != 3) mo_ = min(mo_, bd3);
                int M = 0;
                M = max(M, (t == 1) ? mo_ : bd1);
                M = max(M, (t == 2) ? mo_ : bd2);
                M = max(M, (t == 3) ? mo_ : bd3);
                if (r * r >= M) break;

                const int r2   = r * r;
                const int itop = i - r;
                const int ibot = i + r;
                const bool okT = (itop >= 0);
                const bool okB = (ibot < HQ);
                const int* rowT = tb + itop * WQ;
                const int* rowB = tb + ibot * WQ;
#pragma unroll 1
                for (int dj = -r; dj <= r; ++dj) {
                    const int jj = j + dj;
                    if ((unsigned)jj >= (unsigned)WQ) continue;
                    const int d2 = r2 + dj * dj;
                    if (okT) {
                        const int v = __ldg(&rowT[jj]);
                        bd0 = min(bd0, (v == 0) ? d2 : BIGD2);
                        bd1 = min(bd1, (v == 1) ? d2 : BIGD2);
                        bd2 = min(bd2, (v == 2) ? d2 : BIGD2);
                        bd3 = min(bd3, (v == 3) ? d2 : BIGD2);
                    }
                    if (okB) {
                        const int v = __ldg(&rowB[jj]);
                        bd0 = min(bd0, (v == 0) ? d2 : BIGD2);
                        bd1 = min(bd1, (v == 1) ? d2 : BIGD2);
                        bd2 = min(bd2, (v == 2) ? d2 : BIGD2);
                        bd3 = min(bd3, (v == 3) ? d2 : BIGD2);
                    }
                }
                const int jl = j - r;
                const int jr = j + r;
                const bool okL = (jl >= 0);
                const bool okR = (jr < WQ);
#pragma unroll 1
                for (int di = -r + 1; di <= r - 1; ++di) {
                    const int ii = i + di;
                    if ((unsigned)ii >= (unsigned)HQ) continue;
                    const int d2  = di * di + r2;
                    const int* row = tb + ii * WQ;
                    if (okL) {
                        const int v = __ldg(&row[jl]);
                        bd0 = min(bd0, (v == 0) ? d2 : BIGD2);
                        bd1 = min(bd1, (v == 1) ? d2 : BIGD2);
                        bd2 = min(bd2, (v == 2) ? d2 : BIGD2);
                        bd3 = min(bd3, (v == 3) ? d2 : BIGD2);
                    }
                    if (okR) {
                        const int v = __ldg(&row[jr]);
                        bd0 = min(bd0, (v == 0) ? d2 : BIGD2);
                        bd1 = min(bd1, (v == 1) ? d2 : BIGD2);
                        bd2 = min(bd2, (v == 2) ? d2 : BIGD2);
                        bd3 = min(bd3, (v == 3) ? d2 : BIGD2);
                    }
                }
            }
            mo = BIGD2;
            if (t != 0) mo = min(mo, bd0);
            if (t != 1) mo = min(mo, bd1);
            if (t != 2) mo = min(mo, bd2);
            if (t != 3) mo = min(mo, bd3);
            n1 = (t == 1) ? mo : bd1;
            n2 = (t == 2) ? mo : bd2;
            n3 = (t == 3) ? mo : bd3;
        }

        // --- distances: LUT for certified range, rare branch otherwise ---
        float d1f = ssq[min(n1, 19)];
        float d2f = ssq[min(n2, 19)];
        float d3f = ssq[min(n3, 19)];
        if (max(n1, max(n2, n3)) > 18) {         // ~never (warp-skipped)
            d1f = (n1 <= 18) ? d1f : ((n1 < BIGD2) ? sqrtf((float)n1) : 0.0f);
            d2f = (n2 <= 18) ? d2f : ((n2 < BIGD2) ? sqrtf((float)n2) : 0.0f);
            d3f = (n3 <= 18) ? d3f : ((n3 < BIGD2) ? sqrtf((float)n3) : 0.0f);
        }

        // --- softmax from prefetched smem (no max-sub; |logits| small) ---
        const float wv = sbuf[16 + pr][j];
        const float e0 = __expf(sbuf[pr * 4 + 0][j]);
        const float e1 = __expf(sbuf[pr * 4 + 1][j]);
        const float e2 = __expf(sbuf[pr * 4 + 2][j]);
        const float e3 = __expf(sbuf[pr * 4 + 3][j]);
        const float rd = __fdividef(1.0f, e0 + e1 + e2 + e3);

        float s = fabsf(e1 * rd - ((t == 1) ? 1.0f : 0.0f)) * d1f;
        s      += fabsf(e2 * rd - ((t == 2) ? 1.0f : 0.0f)) * d2f;
        s      += fabsf(e3 * rd - ((t == 3) ? 1.0f : 0.0f)) * d3f;
        acc = fmaf(s, wv, acc);
    }

    // --- block reduction -> per-block partial (fixed order, no atomics) ---
#pragma unroll
    for (int o = 16; o > 0; o >>= 1)
        acc += __shfl_down_sync(0xffffffffu, acc, o);
    if (l == 0) sa[w] = acc;
    __syncthreads();
    if (j == 0) {
        float s = 0.0f;
#pragma unroll
        for (int k = 0; k < 8; ++k) s += sa[k];
        g_partial[blk] = s;
    }

    // --- last-block deterministic finalize ---
    __shared__ unsigned ticket;
    __threadfence();
    if (j == 0) ticket = atomicAdd(&g_done, 1u);
    __syncthreads();
    if (ticket == NBLK - 1) {
        __threadfence();
        __shared__ double sd[256];
        double s = 0.0;
        for (int k = j; k < NBLK; k += 256)
            s += (double)g_partial[k];              // fixed order
        sd[j] = s;
        __syncthreads();
#pragma unroll
        for (int st = 128; st > 0; st >>= 1) {
            if (j < st) sd[j] += sd[j + st];
            __syncthreads();
        }
        if (j == 0) {
            out[0] = (float)(sd[0] / (3.0 * (double)NPIX));
            g_done = 0;                             // restore invariant
        }
    }
}

// ---------------------------------------------------------------------------
extern "C" void kernel_launch(void* const* d_in, const int* in_sizes, int n_in,
                              void* d_out, int out_size) {
    const float* pred   = (const float*)d_in[0];
    const int*   target = (const int*)d_in[1];
    const float* wgt    = (const float*)d_in[2];
    float* out = (float*)d_out;
    (void)in_sizes; (void)n_in; (void)out_size;

    cwbl_kernel<<<NBLK, 256>>>(pred, target, wgt, out);
}